// round 14
// baseline (speedup 1.0000x reference)
#include <cuda_runtime.h>
#include <cuda_fp16.h>
#include <math.h>
#include <stdint.h>

// Problem constants
#define Bn   64
#define Td   256
#define Tp   1024
#define NB   (Bn * 256)
#define NEGV (-1e9f)
#define AL   __align__(256)

// ---------------- device scratch ----------------
__device__ AL __half g_F1h[Td * Tp];
__device__ AL __half g_F2h[Tp * Td];
__device__ AL __half g_Wp1h[384 * 128];     // rows: k0,v0,k1,v1,...,q0..q127
__device__ AL __half g_Wp2h[384 * 128];
__device__ AL float g_bp1[384], g_bp2[384];
__device__ AL __half g_Wodh[128 * 128];
__device__ AL __half g_Woph[128 * 128];
__device__ AL float g_Q1[Bn * Tp * 128];    // dense q projections
__device__ AL float g_Q2[Bn * Td * 128];
__device__ AL __half g_KV1th[NB * Tp];      // rows b*256+2d(ev)/2d+1(e), cols j
__device__ AL __half g_KV2th[NB * Td];
__device__ AL float g_base1[NB], g_base2[NB];   // interleaved [b*256 + 2d + {0,1}]
__device__ AL __half g_Y1h[Bn * Td * 128];
__device__ AL __half g_Y2h[Bn * Tp * 128];
__device__ AL unsigned g_ob1[Bn * 128], g_ob2[Bn * 128];

// ---------------- helpers ----------------
__device__ __forceinline__ unsigned f2key(float f) {
    unsigned u = __float_as_uint(f);
    return (u & 0x80000000u) ? ~u : (u | 0x80000000u);
}
__device__ __forceinline__ float key2f(unsigned u) {
    unsigned b = (u & 0x80000000u) ? (u ^ 0x80000000u) : ~u;
    return __uint_as_float(b);
}
__device__ __forceinline__ void mma16816(float* d, const uint32_t* a,
                                         uint32_t b0, uint32_t b1) {
    asm volatile(
        "mma.sync.aligned.m16n8k16.row.col.f32.f16.f16.f32 "
        "{%0,%1,%2,%3}, {%4,%5,%6,%7}, {%8,%9}, {%0,%1,%2,%3};"
        : "+f"(d[0]), "+f"(d[1]), "+f"(d[2]), "+f"(d[3])
        : "r"(a[0]), "r"(a[1]), "r"(a[2]), "r"(a[3]), "r"(b0), "r"(b1));
}
__device__ __forceinline__ void ldsm4(uint32_t* r, const __half* p) {
    uint32_t a = (uint32_t)__cvta_generic_to_shared(p);
    asm volatile("ldmatrix.sync.aligned.m8n8.x4.shared.b16 {%0,%1,%2,%3}, [%4];"
                 : "=r"(r[0]), "=r"(r[1]), "=r"(r[2]), "=r"(r[3]) : "r"(a));
}
// 8 fp32 -> 8 fp16 packed (identical rounding to k_half path)
__device__ __forceinline__ uint4 f8h8(float4 u, float4 v) {
    uint32_t hh[4];
    __half2 p;
    p = __floats2half2_rn(u.x, u.y); hh[0] = *(uint32_t*)&p;
    p = __floats2half2_rn(u.z, u.w); hh[1] = *(uint32_t*)&p;
    p = __floats2half2_rn(v.x, v.y); hh[2] = *(uint32_t*)&p;
    p = __floats2half2_rn(v.z, v.w); hh[3] = *(uint32_t*)&p;
    return make_uint4(hh[0], hh[1], hh[2], hh[3]);
}

// Per-direction GEMM argument bundle (merged dual launches)
struct GArgs {
    const __half* A;     // [M,K] fp16 row-major (CVT=0)
    const float*  Af;    // [M,K] fp32 row-major (CVT=1)
    const __half* B;     // [N,K] fp16 row-major
    const float*  F0;    // MODE1: dense q; MODE3: packed bias
    const float*  F1;    // MODE1: base
    const int*    I;     // mask
    float*        oF;    // MODE3: dense q out
    __half*       oH;    // MODE1: Y out; MODE3: KV out
    unsigned*     oU;    // MODE2: ob
    float*        oB;    // MODE3: base sums
    int K, lda, ldb, ldx, Mtot;
};

// ---------------- fp16 tensor-core GEMM (single product), fused epilogues ----
// Dual-problem launch: blockIdx.y < ysplit -> g1, else g2.
// Double-buffered smem stages (2 x 16KB), ONE barrier per k-iter.
// CVT=1: A is fp32 in global; convert to fp16 during smem store (rounding
//        identical to the old standalone convert kernel).
// MODE 1: fused AFT y epilogue; smem-staged coalesced fp16 Y writeout.
// MODE 2: fused masked max -> atomicMax oU (I=mask, ldx=SEQ).
// MODE 3: fused projection epilogue (KV build + base sums + dense q).
// Tile 128x128x32, 256 threads, 8 warps (4m x 2n), warp tile 32x64.
// smem: row r, 16B chunk c -> phys chunk = c ^ ((r>>1)&3).
template <int MODE, int CVT>
__global__ __launch_bounds__(256, 2) void gemm_dual(GArgs g1, GArgs g2, int ysplit)
{
    extern __shared__ __align__(16) __half dsm[];

    GArgs a;
    int yb;
    if ((int)blockIdx.y < ysplit) { a = g1; yb = blockIdx.y; }
    else                          { a = g2; yb = blockIdx.y - ysplit; }

    const int tid  = threadIdx.x;
    const int lane = tid & 31;
    const int wid  = tid >> 5;
    const int wm   = (wid >> 1) * 32;
    const int wn   = (wid & 1) * 64;
    const int brow = yb * 128;
    const int bcol = blockIdx.x * 128;

    const int lr  = tid >> 2;
    const int lc  = tid & 3;
    const int so0 = lr * 32 + ((lc ^ ((lr >> 1) & 3)) * 8);
    const int so1 = (lr + 64) * 32 + ((lc ^ (((lr + 64) >> 1) & 3)) * 8);

    const __half* gA0 = CVT ? (const __half*)0
                            : (a.A + (size_t)(brow + lr) * a.lda + lc * 8);
    const float*  gAf = CVT ? (a.Af + (size_t)(brow + lr) * a.lda + lc * 8)
                            : (const float*)0;
    const __half* gB0 = a.B + (size_t)(bcol + lr) * a.ldb + lc * 8;
    const size_t a64 = (size_t)64 * a.lda, b64 = (size_t)64 * a.ldb;

    uint4 ra0[2], rb0[2];
    float4 fa[2][2];
    if (CVT) {
        fa[0][0] = *(const float4*)(gAf);
        fa[0][1] = *(const float4*)(gAf + 4);
        fa[1][0] = *(const float4*)(gAf + a64);
        fa[1][1] = *(const float4*)(gAf + a64 + 4);
    } else {
        ra0[0] = *(const uint4*)(gA0);
        ra0[1] = *(const uint4*)(gA0 + a64);
    }
    rb0[0] = *(const uint4*)(gB0); rb0[1] = *(const uint4*)(gB0 + b64);

    float acc[2][8][4] = {};

    const int arow_b = (lane & 7) + ((lane >> 3) & 1) * 8;
    const int achk_b = (lane >> 4);
    const int brow_b = (lane & 7) + (lane >> 4) * 8;
    const int bchk_b = (lane >> 3) & 1;

    const int iters = a.K >> 5;
    for (int i = 0; i < iters; i++) {
        const int k0 = 32 * i;
        __half* sA0 = dsm + (i & 1) * 8192;      // stage: A at +0, B at +4096
        __half* sB0 = sA0 + 4096;
        if (CVT) {
            *(uint4*)&sA0[so0] = f8h8(fa[0][0], fa[0][1]);
            *(uint4*)&sA0[so1] = f8h8(fa[1][0], fa[1][1]);
        } else {
            *(uint4*)&sA0[so0] = ra0[0];
            *(uint4*)&sA0[so1] = ra0[1];
        }
        *(uint4*)&sB0[so0] = rb0[0]; *(uint4*)&sB0[so1] = rb0[1];
        __syncthreads();

        if (k0 + 32 < a.K) {
            if (CVT) {
                fa[0][0] = *(const float4*)(gAf + k0 + 32);
                fa[0][1] = *(const float4*)(gAf + k0 + 36);
                fa[1][0] = *(const float4*)(gAf + a64 + k0 + 32);
                fa[1][1] = *(const float4*)(gAf + a64 + k0 + 36);
            } else {
                ra0[0] = *(const uint4*)(gA0 + k0 + 32);
                ra0[1] = *(const uint4*)(gA0 + a64 + k0 + 32);
            }
            rb0[0] = *(const uint4*)(gB0 + k0 + 32);
            rb0[1] = *(const uint4*)(gB0 + b64 + k0 + 32);
        }

        #pragma unroll
        for (int ck = 0; ck < 2; ck++) {
            uint32_t af[2][4];
            #pragma unroll
            for (int mt = 0; mt < 2; mt++) {
                int row = wm + mt * 16 + arow_b;
                int chk = 2 * ck + achk_b;
                int off = row * 32 + ((chk ^ ((row >> 1) & 3)) * 8);
                ldsm4(af[mt], &sA0[off]);
            }
            #pragma unroll
            for (int ntp = 0; ntp < 4; ntp++) {
                int row = wn + ntp * 16 + brow_b;
                int chk = 2 * ck + bchk_b;
                int off = row * 32 + ((chk ^ ((row >> 1) & 3)) * 8);
                uint32_t bf0[4];
                ldsm4(bf0, &sB0[off]);
                #pragma unroll
                for (int mt = 0; mt < 2; mt++) {
                    mma16816(acc[mt][2 * ntp],     af[mt], bf0[0], bf0[1]);
                    mma16816(acc[mt][2 * ntp + 1], af[mt], bf0[2], bf0[3]);
                }
            }
        }
    }

    const int g = lane >> 2;
    const int c = lane & 3;

    if (MODE == 1) {
        __syncthreads();                      // all warps past last compute
        const int b  = bcol >> 8;
        const int d0 = (bcol & 128) >> 1;     // 0 or 64
        __half* sy = dsm;                     // [128][72] staging
        #pragma unroll
        for (int mt = 0; mt < 2; mt++) {
            #pragma unroll
            for (int nt = 0; nt < 8; nt++) {
                int col = bcol + wn + nt * 8 + 2 * c;
                int d = (col & 255) >> 1;
                int dl = (wn + nt * 8 + 2 * c) >> 1;   // 0..63
                float2 bs = *(const float2*)&a.F1[col];
                #pragma unroll
                for (int r2 = 0; r2 < 2; r2++) {
                    int rowl = wm + mt * 16 + g + 8 * r2;
                    int rr = brow + rowl;
                    float num = acc[mt][nt][2 * r2]     + bs.x;
                    float den = acc[mt][nt][2 * r2 + 1] + bs.y;
                    float q = a.F0[((size_t)b * a.Mtot + rr) * 128 + d];
                    float sg = 1.f / (1.f + expf(-q));
                    sy[rowl * 72 + dl] = __float2half(sg * num / den);
                }
            }
        }
        __syncthreads();
        int rl = tid >> 1, part = (tid & 1) * 32;
        const __half* src = &sy[rl * 72 + part];
        __half* dst = a.oH + ((size_t)b * a.Mtot + brow + rl) * 128 + d0 + part;
        #pragma unroll
        for (int u = 0; u < 4; u++)
            *(uint4*)(dst + 8 * u) = *(const uint4*)(src + 8 * u);
    } else if (MODE == 2) {
        const int SEQ = a.ldx;
        const int b = brow / SEQ;
        int msk[2][2];
        #pragma unroll
        for (int mt = 0; mt < 2; mt++) {
            msk[mt][0] = a.I[brow + wm + mt * 16 + g];
            msk[mt][1] = a.I[brow + wm + mt * 16 + g + 8];
        }
        #pragma unroll
        for (int nt = 0; nt < 8; nt++) {
            float m0 = -3.0e38f, m1 = -3.0e38f;
            #pragma unroll
            for (int mt = 0; mt < 2; mt++) {
                if (msk[mt][0]) { m0 = fmaxf(m0, acc[mt][nt][0]); m1 = fmaxf(m1, acc[mt][nt][1]); }
                if (msk[mt][1]) { m0 = fmaxf(m0, acc[mt][nt][2]); m1 = fmaxf(m1, acc[mt][nt][3]); }
            }
            #pragma unroll
            for (int off = 4; off < 32; off <<= 1) {
                m0 = fmaxf(m0, __shfl_xor_sync(0xffffffffu, m0, off));
                m1 = fmaxf(m1, __shfl_xor_sync(0xffffffffu, m1, off));
            }
            if (g == 0) {
                int col = wn + nt * 8 + 2 * c;
                if (m0 > -2.9e38f) atomicMax(&a.oU[b * 128 + col],     f2key(m0));
                if (m1 > -2.9e38f) atomicMax(&a.oU[b * 128 + col + 1], f2key(m1));
            }
        }
    } else {
        // MODE 3: fused projection epilogue
        const int SEQ = a.ldx;
        const int b   = brow / SEQ;
        const int j0  = brow - b * SEQ;
        __half* st = dsm;   // [128][136] transpose buffer (overlaps loop smem)
        if (bcol < 256) {
            __syncthreads();
            int msk[2][2];
            #pragma unroll
            for (int mt = 0; mt < 2; mt++) {
                msk[mt][0] = a.I[brow + wm + mt * 16 + g];
                msk[mt][1] = a.I[brow + wm + mt * 16 + g + 8];
            }
            #pragma unroll
            for (int nt = 0; nt < 8; nt++) {
                int colp = wn + nt * 8 + 2 * c;   // local even col (k)
                int dl   = colp >> 1;             // 0..63
                float bk = a.F0[bcol + colp];
                float bv = a.F0[bcol + colp + 1];
                float sev = 0.f, se = 0.f;
                #pragma unroll
                for (int mt = 0; mt < 2; mt++) {
                    #pragma unroll
                    for (int r2 = 0; r2 < 2; r2++) {
                        int rowl = wm + mt * 16 + g + 8 * r2;
                        float kk = acc[mt][nt][2 * r2]     + bk;
                        float vv = acc[mt][nt][2 * r2 + 1] + bv;
                        float e  = msk[mt][r2] ? expf(kk) : 0.f;
                        float ev = e * vv;
                        sev += ev; se += e;
                        st[(2 * dl)     * 136 + rowl] = __float2half(ev);
                        st[(2 * dl + 1) * 136 + rowl] = __float2half(e);
                    }
                }
                sev += __shfl_xor_sync(0xffffffffu, sev, 4);
                se  += __shfl_xor_sync(0xffffffffu, se, 4);
                sev += __shfl_xor_sync(0xffffffffu, sev, 8);
                se  += __shfl_xor_sync(0xffffffffu, se, 8);
                sev += __shfl_xor_sync(0xffffffffu, sev, 16);
                se  += __shfl_xor_sync(0xffffffffu, se, 16);
                if (g == 0) {
                    atomicAdd(&a.oB[b * 256 + bcol + 2 * dl],     sev);
                    atomicAdd(&a.oB[b * 256 + bcol + 2 * dl + 1], se);
                }
            }
            __syncthreads();
            int rl = tid >> 1, jh = (tid & 1) * 64;
            const __half* src = &st[rl * 136 + jh];
            __half* dst = a.oH + ((size_t)(b * 256 + bcol + rl)) * SEQ + j0 + jh;
            #pragma unroll
            for (int u = 0; u < 8; u++)
                *(uint4*)(dst + 8 * u) = *(const uint4*)(src + 8 * u);
        } else {
            // q part -> dense fp32 [row*128 + qd]
            #pragma unroll
            for (int mt = 0; mt < 2; mt++) {
                #pragma unroll
                for (int nt = 0; nt < 8; nt++) {
                    int colp = wn + nt * 8 + 2 * c;
                    float bx = a.F0[256 + colp], by = a.F0[256 + colp + 1];
                    int row = brow + wm + mt * 16 + g;
                    float2 v0, v1;
                    v0.x = acc[mt][nt][0] + bx; v0.y = acc[mt][nt][1] + by;
                    v1.x = acc[mt][nt][2] + bx; v1.y = acc[mt][nt][3] + by;
                    *(float2*)&a.oF[(size_t)row * 128 + colp]       = v0;
                    *(float2*)&a.oF[(size_t)(row + 8) * 128 + colp] = v1;
                }
            }
        }
    }
}

// ---------------- small prep kernel (init + expf + Wo converts + packs) ------
// blocks: [0,64) init | [64,320) expf | [320,328) half(Wpd) | [328,336) half(Wpp) |
// [336,528) pack1 | [528,720) pack2
__device__ __forceinline__ void prep_half(const float* x, __half* h, int i, int n8) {
    if (i >= n8) return;
    float4 v0 = ((const float4*)x)[2 * i];
    float4 v1 = ((const float4*)x)[2 * i + 1];
    ((uint4*)h)[i] = f8h8(v0, v1);
}
__device__ __forceinline__ void prep_pack(const float* Wk, const float* bk,
                                          const float* Wv, const float* bv,
                                          const float* Wq, const float* bq,
                                          __half* Wh, float* bp, int i) {
    if (i < 384 * 128) {
        int r = i >> 7, cc = i & 127;
        const float* s;
        int sr;
        if (r < 256) { s = (r & 1) ? Wv : Wk; sr = r >> 1; }
        else         { s = Wq; sr = r - 256; }
        Wh[i] = __float2half(s[sr * 128 + cc]);
    }
    if (i < 384) {
        bp[i] = (i < 256) ? ((i & 1) ? bv[i >> 1] : bk[i >> 1]) : bq[i - 256];
    }
}

__global__ void k_prep(
    const float* __restrict__ pb,
    const float* Wkp, const float* bkp, const float* Wvp, const float* bvp,
    const float* Wqp, const float* bqp,
    const float* Wkd, const float* bkd, const float* Wvd, const float* bvd,
    const float* Wqd, const float* bqd,
    const float* Wpd, const float* Wpp,
    __half* F1, __half* F2,
    __half* Wp1h, __half* Wp2h, float* bp1, float* bp2,
    __half* Wodh, __half* Woph,
    unsigned* ob1, unsigned* ob2, float* base1, float* base2)
{
    __shared__ float s[32][33];
    const int bid = blockIdx.x;
    const int tid = threadIdx.x;
    if (bid < 64) {
        int i = bid * 256 + tid;
        if (i < Bn * 128) {
            unsigned k = f2key(NEGV);
            ob1[i] = k; ob2[i] = k;
        }
        base1[i] = 0.f; base2[i] = 0.f;
    } else if (bid < 320) {
        int t = bid - 64;
        int j0 = (t & 31) * 32, i0 = (t >> 5) * 32;
        int tx = tid & 31, ty = tid >> 5;
        #pragma unroll
        for (int r = ty; r < 32; r += 8) {
            float v = expf(pb[(i0 + r) * 1024 + j0 + tx]) - 1.0f;
            F1[(i0 + r) * Tp + j0 + tx] = __float2half(v);
            s[r][tx] = v;
        }
        __syncthreads();
        #pragma unroll
        for (int r = ty; r < 32; r += 8)
            F2[(j0 + r) * Td + i0 + tx] = __float2half(s[tx][r]);
    } else if (bid < 328) {
        prep_half(Wpd, Wodh, (bid - 320) * 256 + tid, 128 * 128 / 8);
    } else if (bid < 336) {
        prep_half(Wpp, Woph, (bid - 328) * 256 + tid, 128 * 128 / 8);
    } else if (bid < 528) {
        prep_pack(Wkp, bkp, Wvp, bvp, Wqp, bqp, Wp1h, bp1, (bid - 336) * 256 + tid);
    } else {
        prep_pack(Wkd, bkd, Wvd, bvd, Wqd, bqd, Wp2h, bp2, (bid - 528) * 256 + tid);
    }
}

__global__ void k_out(const unsigned* __restrict__ ob1, const unsigned* __restrict__ ob2,
                      const float* __restrict__ bpd, const float* __restrict__ bpp,
                      float* __restrict__ out) {
    int i = blockIdx.x * 256 + threadIdx.x;
    if (i < Bn * 128) {
        int t = i & 127;
        out[i]            = key2f(ob1[i]) + bpd[t];
        out[Bn * 128 + i] = key2f(ob2[i]) + bpp[t];
    }
}

// ---------------- launch ----------------
#define SYM(p, s) cudaGetSymbolAddress((void**)&p, s)

extern "C" void kernel_launch(void* const* d_in, const int* in_sizes, int n_in,
                              void* d_out, int out_size) {
    const float* smiles  = (const float*)d_in[0];
    const float* protein = (const float*)d_in[1];
    const int*   smask   = (const int*)d_in[2];
    const int*   pmask   = (const int*)d_in[3];
    const float* pb      = (const float*)d_in[4];
    const float* Wqd = (const float*)d_in[5],  *bqd = (const float*)d_in[6];
    const float* Wkp = (const float*)d_in[7],  *bkp = (const float*)d_in[8];
    const float* Wvp = (const float*)d_in[9],  *bvp = (const float*)d_in[10];
    const float* Wqp = (const float*)d_in[11], *bqp = (const float*)d_in[12];
    const float* Wkd = (const float*)d_in[13], *bkd = (const float*)d_in[14];
    const float* Wvd = (const float*)d_in[15], *bvd = (const float*)d_in[16];
    const float* Wpd = (const float*)d_in[17], *bpd = (const float*)d_in[18];
    const float* Wpp = (const float*)d_in[19], *bpp = (const float*)d_in[20];
    float* out = (float*)d_out;

    __half *F1h, *F2h, *Wp1h, *Wp2h;
    __half *Wodh, *Woph, *KV1th, *KV2th, *Y1h, *Y2h;
    float *bp1, *bp2, *Q1, *Q2, *base1, *base2;
    unsigned *ob1, *ob2;
    SYM(F1h, g_F1h);   SYM(F2h, g_F2h);
    SYM(Wp1h, g_Wp1h); SYM(Wp2h, g_Wp2h);
    SYM(bp1, g_bp1);   SYM(bp2, g_bp2);
    SYM(Wodh, g_Wodh); SYM(Woph, g_Woph);
    SYM(Q1, g_Q1);     SYM(Q2, g_Q2);
    SYM(KV1th, g_KV1th); SYM(KV2th, g_KV2th);
    SYM(base1, g_base1); SYM(base2, g_base2);
    SYM(Y1h, g_Y1h);   SYM(Y2h, g_Y2h);
    SYM(ob1, g_ob1);   SYM(ob2, g_ob2);

    const int SM_PROJ = 136 * 128 * 2;   // 34816 (MODE3 transpose; loop uses 32KB)
    const int SM_MAIN = 2 * 16384;       // 32768
    const int SM_OUT  = 2 * 16384;       // 32768

    // small prep launch (init + expf + Wo converts + packs)
    k_prep<<<720, 256>>>(pb,
                         Wkp, bkp, Wvp, bvp, Wqp, bqp,
                         Wkd, bkd, Wvd, bvd, Wqd, bqd,
                         Wpd, Wpp,
                         F1h, F2h, Wp1h, Wp2h, bp1, bp2,
                         Wodh, Woph, ob1, ob2, base1, base2);

    GArgs z = {};

    // merged projections (MODE 3, CVT=1: X fp32 loaded+converted in-kernel)
    {
        GArgs p1 = z, p2 = z;
        p1.Af = protein; p1.B = Wp1h; p1.F0 = bp1; p1.I = pmask;
        p1.oF = Q1; p1.oH = KV1th; p1.oB = base1;
        p1.K = 128; p1.lda = 128; p1.ldb = 128; p1.ldx = Tp; p1.Mtot = Tp;
        p2.Af = smiles; p2.B = Wp2h; p2.F0 = bp2; p2.I = smask;
        p2.oF = Q2; p2.oH = KV2th; p2.oB = base2;
        p2.K = 128; p2.lda = 128; p2.ldb = 128; p2.ldx = Td; p2.Mtot = Td;
        gemm_dual<3, 1><<<dim3(3, 512 + 128), 256, SM_PROJ>>>(p1, p2, 512);
    }

    // merged main AFT GEMMs (MODE 1): dir1 heavy (K=1024, 2 y-tiles) first
    {
        GArgs m1 = z, m2 = z;
        m1.A = F1h; m1.B = KV1th; m1.F0 = Q2; m1.F1 = base1; m1.oH = Y1h;
        m1.K = Tp; m1.lda = Tp; m1.ldb = Tp; m1.Mtot = Td;
        m2.A = F2h; m2.B = KV2th; m2.F0 = Q1; m2.F1 = base2; m2.oH = Y2h;
        m2.K = Td; m2.lda = Td; m2.ldb = Td; m2.Mtot = Tp;
        gemm_dual<1, 0><<<dim3(NB / 128, 2 + 8), 256, SM_MAIN>>>(m1, m2, 2);
    }

    // merged output projections (MODE 2) with fused masked-max
    {
        GArgs o1 = z, o2 = z;
        o1.A = Y1h; o1.B = Wodh; o1.I = smask; o1.oU = ob1;
        o1.K = 128; o1.lda = 128; o1.ldb = 128; o1.ldx = Td;
        o2.A = Y2h; o2.B = Woph; o2.I = pmask; o2.oU = ob2;
        o2.K = 128; o2.lda = 128; o2.ldb = 128; o2.ldx = Tp;
        gemm_dual<2, 0><<<dim3(1, 128 + 512), 256, SM_OUT>>>(o1, o2, 128);
    }

    // decode + add output bias
    k_out<<<(Bn * 128 + 255) / 256, 256>>>(ob1, ob2, bpd, bpp, out);
}